// round 17
// baseline (speedup 1.0000x reference)
#include <cuda_runtime.h>
#include <cuda_bf16.h>
#include <cuda_fp16.h>
#include <stdint.h>

#define NP     4096
#define DF     256
#define TOPK   100
#define NBINS  2048      // coarse: fp16 bits >> 4
#define NCODES 32768     // fine: full positive fp16 code space
#define PREBLK 128       // sampled 128x64 tiles (injective (p-tile, q-half) pairs)
#define MAINBLK (32 * 32)

// ---- scratch (static device globals; no allocation in kernel_launch) ----
__device__ __nv_bfloat16 g_c1b[NP * DF];
__device__ __nv_bfloat16 g_c2b[NP * DF];
__device__ float         g_sq1[NP];
__device__ float         g_sq2[NP];
__device__ unsigned int  g_hist[NBINS];            // sampled coarse histogram (1/16)
__device__ unsigned int  g_hist2[NCODES];          // exact per-code counts (candidates)
__device__ int           g_threshBin;
__device__ unsigned int  g_cntPre;
__device__ unsigned int  g_cntMain;

__device__ __forceinline__ uint32_t smem_u32(const void* p) {
    uint32_t a;
    asm("{ .reg .u64 t; cvta.to.shared.u64 t, %1; cvt.u32.u64 %0, t; }" : "=r"(a) : "l"(p));
    return a;
}

#define CP_ASYNC16(dst, src)                                                   \
    asm volatile("cp.async.cg.shared.global [%0], [%1], 16;" :: "r"(dst), "l"(src))
#define CP_COMMIT()  asm volatile("cp.async.commit_group;" ::: "memory")
#define CP_WAIT(n)   asm volatile("cp.async.wait_group %0;" :: "n"(n) : "memory")

#define LDSM_X4(r0, r1, r2, r3, addr)                                          \
    asm volatile("ldmatrix.sync.aligned.m8n8.x4.shared.b16 {%0,%1,%2,%3}, [%4];" \
        : "=r"(r0), "=r"(r1), "=r"(r2), "=r"(r3) : "r"(addr))

#define MMA16816(c, a0, a1, a2, a3, b0, b1)                                    \
    asm volatile("mma.sync.aligned.m16n8k16.row.col.f32.bf16.bf16.f32 "        \
        "{%0,%1,%2,%3}, {%4,%5,%6,%7}, {%8,%9}, {%0,%1,%2,%3};"                \
        : "+f"((c)[0]), "+f"((c)[1]), "+f"((c)[2]), "+f"((c)[3])               \
        : "r"(a0), "r"(a1), "r"(a2), "r"(a3), "r"(b0), "r"(b1))

// ---- main-kernel SMEM layout (bytes) ----
#define SM_SP    0                          // 128 f32
#define SM_SQ    512                        // 128 f32
#define SM_T     1024
#define STAGEB   32768                      // A(16K)+B(16K)
#define SM_TOT   (SM_T + 2 * STAGEB)        // 66560 -> 2 CTAs/SM
// ---- pre-kernel SMEM layout ----
#define PSM_HIST 0                          // 8192
#define PSM_SP   8192                       // 128 f32
#define PSM_SQ   8704                       // 64 f32
#define PSM_T    9216
#define PSTAGEB  24576                      // A(16K)+B(8K)
#define PSM_TOT  (PSM_T + 2 * PSTAGEB)      // 58368

// ================= kernels =================

// gather picked rows (-> bf16) + fp32 norms; fused zeroing of hists/counters
__global__ __launch_bounds__(256) void k_gather(const float* __restrict__ fm,
                                                const int* __restrict__ ids1,
                                                const int* __restrict__ ids2) {
    if (blockIdx.y == 0 && blockIdx.x < 34) {       // fused init: 34816 words
        int id = blockIdx.x * 256 + threadIdx.x;
        #pragma unroll
        for (int j = 0; j < 4; j++) {
            int wI = id * 4 + j;
            if (wI < NBINS) g_hist[wI] = 0u;
            else if (wI < NBINS + NCODES) g_hist2[wI - NBINS] = 0u;
        }
        if (blockIdx.x == 0 && threadIdx.x == 0) { g_cntPre = 0u; g_cntMain = 0u; }
    }

    const int g = threadIdx.x >> 6;                 // 4 rows per block
    const int lt = threadIdx.x & 63;
    const int row = blockIdx.x * 4 + g;
    const int* ids = blockIdx.y ? ids2 : ids1;
    __nv_bfloat16* C = blockIdx.y ? g_c2b : g_c1b;
    float*        SQ = blockIdx.y ? g_sq2 : g_sq1;

    int id = ids[row];
    float4 v = ((const float4*)(fm + (size_t)id * DF))[lt];

    unsigned lo = ((unsigned)__bfloat16_as_ushort(__float2bfloat16(v.y)) << 16) |
                   (unsigned)__bfloat16_as_ushort(__float2bfloat16(v.x));
    unsigned hi = ((unsigned)__bfloat16_as_ushort(__float2bfloat16(v.w)) << 16) |
                   (unsigned)__bfloat16_as_ushort(__float2bfloat16(v.z));
    *(uint2*)&C[(size_t)row * DF + lt * 4] = make_uint2(lo, hi);

    float s = v.x * v.x + v.y * v.y + v.z * v.z + v.w * v.w;
    #pragma unroll
    for (int o = 16; o; o >>= 1) s += __shfl_down_sync(0xffffffffu, s, o);
    __shared__ float ws[8];
    if ((threadIdx.x & 31) == 0) ws[threadIdx.x >> 5] = s;
    __syncthreads();
    if (lt == 0) SQ[row] = ws[g * 2] + ws[g * 2 + 1];
}

// ---------------- sampled pre-pass: 128x64 tiles + coarse hist + fused thresh ----
__device__ __forceinline__ void pre_load(uint32_t sb, int t, int p0, int q0,
                                         int stg, int kc) {
    const uint32_t baseA = sb + PSM_T + stg * PSTAGEB;
    #pragma unroll
    for (int i = 0; i < 4; i++) {                   // A: 128 rows
        int idx = i * 256 + t;
        int row = idx >> 3, c = idx & 7;
        uint32_t off = row * 128 + (((unsigned)(c ^ (row & 7))) << 4);
        CP_ASYNC16(baseA + off, &g_c1b[(size_t)(p0 + row) * DF + kc * 64 + c * 8]);
    }
    #pragma unroll
    for (int i = 0; i < 2; i++) {                   // B: 64 rows
        int idx = i * 256 + t;
        int row = idx >> 3, c = idx & 7;
        uint32_t off = row * 128 + (((unsigned)(c ^ (row & 7))) << 4);
        CP_ASYNC16(baseA + 16384 + off, &g_c2b[(size_t)(q0 + row) * DF + kc * 64 + c * 8]);
    }
    CP_COMMIT();
}

__global__ __launch_bounds__(256, 2) void k_pre() {
    extern __shared__ char sm[];
    const uint32_t sb = smem_u32(sm);
    const int t = threadIdx.x, lane = t & 31, w = t >> 5;

    const int by = blockIdx.x & 31;                     // p tile
    const int qh = (2 * by + 16 * (blockIdx.x >> 5)) & 63;  // injective q half
    const int p0 = by * 128, q0 = qh * 64;

    pre_load(sb, t, p0, q0, 0, 0);
    pre_load(sb, t, p0, q0, 1, 1);

    unsigned* hist = (unsigned*)(sm + PSM_HIST);
    for (int i = t; i < NBINS; i += 256) hist[i] = 0u;
    if (t < 128)      ((float*)(sm + PSM_SP))[t]      = g_sq1[p0 + t];
    else if (t < 192) ((float*)(sm + PSM_SQ))[t - 128] = g_sq2[q0 + t - 128];

    // 8 warps along M (16 rows each), full 64 cols per warp
    const int mbase = w * 16;
    uint32_t aRow; unsigned aXor;
    const unsigned aCb = lane >> 4, bCb = (lane >> 3) & 1;
    { int row = mbase + (lane & 15); aRow = row * 128; aXor = row & 7; }
    uint32_t bRow[4]; unsigned bXor[4];
    #pragma unroll
    for (int jp = 0; jp < 4; jp++) {
        int row = jp * 16 + (lane & 7) + ((lane >> 4) & 1) * 8;
        bRow[jp] = row * 128; bXor[jp] = row & 7;
    }

    float c[8][4];
    #pragma unroll
    for (int j = 0; j < 8; j++)
        #pragma unroll
        for (int r = 0; r < 4; r++) c[j][r] = 0.f;

    #pragma unroll
    for (int k = 0; k < 4; k++) {
        if (k == 3) CP_WAIT(0); else CP_WAIT(1);
        __syncthreads();
        const uint32_t baseA = sb + PSM_T + (k & 1) * PSTAGEB;
        const uint32_t baseB = baseA + 16384;
        #pragma unroll
        for (int ks = 0; ks < 4; ks++) {
            uint32_t a[4], b[8][2];
            uint32_t offA = ((unsigned)(((ks << 1) | aCb) ^ aXor)) << 4;
            LDSM_X4(a[0], a[1], a[2], a[3], baseA + aRow + offA);
            #pragma unroll
            for (int jp = 0; jp < 4; jp++) {
                uint32_t off = ((unsigned)(((ks << 1) | bCb) ^ bXor[jp])) << 4;
                LDSM_X4(b[2 * jp][0], b[2 * jp][1], b[2 * jp + 1][0], b[2 * jp + 1][1],
                        baseB + bRow[jp] + off);
            }
            #pragma unroll
            for (int j = 0; j < 8; j++)
                MMA16816(c[j], a[0], a[1], a[2], a[3], b[j][0], b[j][1]);
        }
        __syncthreads();
        if (k < 2) pre_load(sb, t, p0, q0, k & 1, k + 2);
    }

    const float* sps = (const float*)(sm + PSM_SP);
    const float* sqs = (const float*)(sm + PSM_SQ);
    const int r0 = mbase + (lane >> 2);
    const float sp0 = sps[r0], sp1 = sps[r0 + 8];
    #pragma unroll
    for (int j = 0; j < 8; j++) {
        const int cl = j * 8 + (lane & 3) * 2;
        const float sq0 = sqs[cl], sq1 = sqs[cl + 1];
        float d0 = fmaxf(sp0 + sq0 - 2.f * c[j][0], 0.f);
        float d1 = fmaxf(sp0 + sq1 - 2.f * c[j][1], 0.f);
        float d2v = fmaxf(sp1 + sq0 - 2.f * c[j][2], 0.f);
        float d3 = fmaxf(sp1 + sq1 - 2.f * c[j][3], 0.f);
        __half2 h01 = __floats2half2_rn(d0, d1);
        __half2 h23 = __floats2half2_rn(d2v, d3);
        unsigned u01 = *(unsigned*)&h01, u23 = *(unsigned*)&h23;
        unsigned b0 = (u01 & 0xFFFFu) >> 4, b1 = u01 >> 20;
        unsigned b2 = (u23 & 0xFFFFu) >> 4, b3 = u23 >> 20;
        if (b0 == b1) atomicAdd(&hist[b0], 2u);
        else { atomicAdd(&hist[b0], 1u); atomicAdd(&hist[b1], 1u); }
        if (b2 == b3) atomicAdd(&hist[b2], 2u);
        else { atomicAdd(&hist[b2], 1u); atomicAdd(&hist[b3], 1u); }
    }
    __syncthreads();
    for (int i = t; i < NBINS; i += 256) {
        unsigned h = hist[i];
        if (h) atomicAdd(&g_hist[i], h);
    }

    // last block computes the threshold (fused k_thresh)
    __shared__ unsigned s_last;
    __threadfence();
    if (t == 0) s_last = (atomicAdd(&g_cntPre, 1u) == PREBLK - 1) ? 1u : 0u;
    __syncthreads();
    if (s_last && w == 0) {
        unsigned cum = 0;
        for (int b0 = NBINS - 1; b0 >= 31; b0 -= 32) {
            unsigned s = g_hist[b0 - lane];
            #pragma unroll
            for (int o = 1; o < 32; o <<= 1) {
                unsigned u = __shfl_up_sync(0xffffffffu, s, o);
                if (lane >= o) s += u;
            }
            unsigned tot = cum + s;
            unsigned ball = __ballot_sync(0xffffffffu, tot >= TOPK);
            if (ball) {
                int fl = __ffs(ball) - 1;
                if (lane == fl) g_threshBin = b0 - fl;
                return;
            }
            cum += __shfl_sync(0xffffffffu, s, 31);
        }
        if (lane == 0) g_threshBin = 0;
    }
}

// ---------------- main pass: GEMM + filtered fine counts + fused select ----
__device__ __forceinline__ void load_chunk(uint32_t sb, int t, int p0, int q0,
                                           int stg, int kc) {
    const uint32_t baseA = sb + SM_T + stg * STAGEB;
    #pragma unroll
    for (int i = 0; i < 4; i++) {
        int idx = i * 256 + t;
        int row = idx >> 3, c = idx & 7;
        uint32_t off = row * 128 + (((unsigned)(c ^ (row & 7))) << 4);
        CP_ASYNC16(baseA + off,         &g_c1b[(size_t)(p0 + row) * DF + kc * 64 + c * 8]);
        CP_ASYNC16(baseA + 16384 + off, &g_c2b[(size_t)(q0 + row) * DF + kc * 64 + c * 8]);
    }
    CP_COMMIT();
}

__global__ __launch_bounds__(256, 2) void k_dist(float* __restrict__ out) {
    extern __shared__ char sm[];
    const uint32_t sb = smem_u32(sm);
    const int t = threadIdx.x, lane = t & 31, w = t >> 5;
    const int p0 = blockIdx.y * 128, q0 = blockIdx.x * 128;

    load_chunk(sb, t, p0, q0, 0, 0);
    load_chunk(sb, t, p0, q0, 1, 1);

    if (t < 128)       ((float*)(sm + SM_SP))[t]       = g_sq1[p0 + t];
    else               ((float*)(sm + SM_SQ))[t - 128] = g_sq2[q0 + t - 128];

    const int mbase = (w & 3) * 32;
    const int nbase = (w >> 2) * 64;

    uint32_t aRow[2], bRow[4];
    unsigned aXor[2], bXor[4];
    const unsigned aCb = lane >> 4, bCb = (lane >> 3) & 1;
    #pragma unroll
    for (int i = 0; i < 2; i++) {
        int row = mbase + i * 16 + (lane & 15);
        aRow[i] = row * 128; aXor[i] = row & 7;
    }
    #pragma unroll
    for (int jp = 0; jp < 4; jp++) {
        int row = nbase + jp * 16 + (lane & 7) + ((lane >> 4) & 1) * 8;
        bRow[jp] = row * 128; bXor[jp] = row & 7;
    }

    float c[2][8][4];
    #pragma unroll
    for (int i = 0; i < 2; i++)
        #pragma unroll
        for (int j = 0; j < 8; j++)
            #pragma unroll
            for (int r = 0; r < 4; r++) c[i][j][r] = 0.f;

    #pragma unroll
    for (int k = 0; k < 4; k++) {
        if (k == 3) CP_WAIT(0); else CP_WAIT(1);
        __syncthreads();
        const uint32_t baseA = sb + SM_T + (k & 1) * STAGEB;
        const uint32_t baseB = baseA + 16384;
        #pragma unroll
        for (int ks = 0; ks < 4; ks++) {
            uint32_t a[2][4], b[8][2];
            #pragma unroll
            for (int i = 0; i < 2; i++) {
                uint32_t off = ((unsigned)(((ks << 1) | aCb) ^ aXor[i])) << 4;
                LDSM_X4(a[i][0], a[i][1], a[i][2], a[i][3], baseA + aRow[i] + off);
            }
            #pragma unroll
            for (int jp = 0; jp < 4; jp++) {
                uint32_t off = ((unsigned)(((ks << 1) | bCb) ^ bXor[jp])) << 4;
                LDSM_X4(b[2 * jp][0], b[2 * jp][1], b[2 * jp + 1][0], b[2 * jp + 1][1],
                        baseB + bRow[jp] + off);
            }
            #pragma unroll
            for (int i = 0; i < 2; i++)
                #pragma unroll
                for (int j = 0; j < 8; j++)
                    MMA16816(c[i][j], a[i][0], a[i][1], a[i][2], a[i][3], b[j][0], b[j][1]);
        }
        __syncthreads();
        if (k < 2) load_chunk(sb, t, p0, q0, k & 1, k + 2);
    }

    const float* sps = (const float*)(sm + SM_SP);
    const float* sqs = (const float*)(sm + SM_SQ);
    const unsigned tc = ((unsigned)g_threshBin) << 4;

    #pragma unroll
    for (int i = 0; i < 2; i++) {
        const int r0 = mbase + i * 16 + (lane >> 2);
        const float sp0 = sps[r0], sp1 = sps[r0 + 8];
        #pragma unroll
        for (int j = 0; j < 8; j++) {
            const int cl = nbase + j * 8 + (lane & 3) * 2;
            const float sq0 = sqs[cl], sq1 = sqs[cl + 1];
            float d0 = fmaxf(sp0 + sq0 - 2.f * c[i][j][0], 0.f);
            float d1 = fmaxf(sp0 + sq1 - 2.f * c[i][j][1], 0.f);
            float d2v = fmaxf(sp1 + sq0 - 2.f * c[i][j][2], 0.f);
            float d3 = fmaxf(sp1 + sq1 - 2.f * c[i][j][3], 0.f);
            __half2 h01 = __floats2half2_rn(d0, d1);
            __half2 h23 = __floats2half2_rn(d2v, d3);
            unsigned u01 = *(unsigned*)&h01, u23 = *(unsigned*)&h23;
            unsigned c0 = u01 & 0xFFFFu, c1 = u01 >> 16;
            unsigned c2 = u23 & 0xFFFFu, c3 = u23 >> 16;
            if (c0 >= tc) atomicAdd(&g_hist2[c0], 1u);
            if (c1 >= tc) atomicAdd(&g_hist2[c1], 1u);
            if (c2 >= tc) atomicAdd(&g_hist2[c2], 1u);
            if (c3 >= tc) atomicAdd(&g_hist2[c3], 1u);
        }
    }

    // fused select: last finishing block scans the fine-code histogram
    __shared__ unsigned s_last;
    __syncthreads();
    __threadfence();
    if (t == 0) s_last = (atomicAdd(&g_cntMain, 1u) == MAINBLK - 1) ? 1u : 0u;
    __syncthreads();
    if (!s_last) return;

    __shared__ unsigned scan[256];
    __shared__ float    part[256];
    const int chi = NCODES - 1 - 128 * t;           // 128 codes per thread, descending
    unsigned csum = 0;
    for (int j = 0; j < 128; j++) csum += g_hist2[chi - j];
    scan[t] = csum;
    __syncthreads();
    #pragma unroll
    for (int o = 1; o < 256; o <<= 1) {
        unsigned v = (t >= o) ? scan[t - o] : 0u;
        __syncthreads();
        if (t >= o) scan[t] += v;
        __syncthreads();
    }
    const unsigned excl = scan[t] - csum;

    float psum = 0.f;
    if (excl < TOPK) {
        unsigned quota = TOPK - excl;
        for (int j = 0; j < 128 && quota; j++) {
            unsigned cc = g_hist2[chi - j];
            if (cc) {
                unsigned take = cc < quota ? cc : quota;
                float val = __half2float(__ushort_as_half((unsigned short)(chi - j)));
                psum += (float)take * sqrtf(val);
                quota -= take;
            }
        }
    }
    part[t] = psum;
    __syncthreads();
    #pragma unroll
    for (int s = 128; s > 0; s >>= 1) {
        if (t < s) part[t] += part[t + s];
        __syncthreads();
    }
    if (t == 0) *out = part[0] / (float)TOPK;
}

extern "C" void kernel_launch(void* const* d_in, const int* in_sizes, int n_in,
                              void* d_out, int out_size) {
    const float* fm   = (const float*)d_in[0];
    const int*   ids1 = (const int*)d_in[1];
    const int*   ids2 = (const int*)d_in[2];
    float* out = (float*)d_out;

    static int smem_set = 0;
    if (!smem_set) {
        cudaFuncSetAttribute(k_dist, cudaFuncAttributeMaxDynamicSharedMemorySize, SM_TOT);
        cudaFuncSetAttribute(k_pre,  cudaFuncAttributeMaxDynamicSharedMemorySize, PSM_TOT);
        smem_set = 1;
    }

    k_gather<<<dim3(NP / 4, 2), 256>>>(fm, ids1, ids2);
    k_pre<<<PREBLK, 256, PSM_TOT>>>();
    k_dist<<<dim3(NP / 128, NP / 128), 256, SM_TOT>>>(out);
}